// round 1
// baseline (speedup 1.0000x reference)
#include <cuda_runtime.h>
#include <math.h>

#define B_ 2
#define T_ 2048
#define C_ 1024
#define H_ 16
#define D_ 64

// Scratch (allocation-free rule: __device__ globals)
__device__ float g_qkv[(size_t)B_ * T_ * 3 * C_];   // [B,T,3C]  ~50 MB
__device__ float g_att[(size_t)B_ * T_ * C_];       // [B,T,C]   ~17 MB

// ---------------------------------------------------------------------------
// Generic fp32 GEMM: C[M,N] = A[M,K] @ B[K,N], all row-major.
// BM=BN=128, BK=8, 256 threads, 8x8 micro-tiles, register prefetch.
// Requires M%128==0, N%128==0, K%8==0 (true for all our shapes).
// ---------------------------------------------------------------------------
__global__ __launch_bounds__(256) void sgemm128(
    const float* __restrict__ A, const float* __restrict__ Bm,
    float* __restrict__ Cm, int M, int N, int K)
{
    __shared__ float As[8][128];
    __shared__ float Bs[8][128];

    const int tid = threadIdx.x;
    const int bm = blockIdx.y * 128;
    const int bn = blockIdx.x * 128;
    const int tm = (tid >> 4) * 8;     // 0..120
    const int tn = (tid & 15) * 8;     // 0..120

    // A tile loader: 128 rows x 8 cols = 256 float4
    const int a_r = tid >> 1;          // 0..127
    const int a_c = (tid & 1) * 4;     // 0 or 4
    // B tile loader: 8 rows x 128 cols = 256 float4
    const int b_r = tid >> 5;          // 0..7
    const int b_c = (tid & 31) * 4;    // 0..124

    const float* Ap = A + (size_t)(bm + a_r) * K + a_c;
    const float* Bp = Bm + (size_t)b_r * N + bn + b_c;

    float4 av = *(const float4*)Ap;
    float4 bv = *(const float4*)Bp;

    float acc[8][8];
    #pragma unroll
    for (int i = 0; i < 8; ++i)
        #pragma unroll
        for (int j = 0; j < 8; ++j) acc[i][j] = 0.f;

    for (int k0 = 0; k0 < K; k0 += 8) {
        // store current tile (A transposed for outer-product access)
        As[a_c + 0][a_r] = av.x;
        As[a_c + 1][a_r] = av.y;
        As[a_c + 2][a_r] = av.z;
        As[a_c + 3][a_r] = av.w;
        *(float4*)&Bs[b_r][b_c] = bv;
        __syncthreads();

        // prefetch next tile into registers (hides global latency)
        if (k0 + 8 < K) {
            av = *(const float4*)(Ap + k0 + 8);
            bv = *(const float4*)(Bp + (size_t)(k0 + 8) * N);
        }

        #pragma unroll
        for (int kk = 0; kk < 8; ++kk) {
            float am[8], bb[8];
            #pragma unroll
            for (int i = 0; i < 8; ++i) am[i] = As[kk][tm + i];
            #pragma unroll
            for (int j = 0; j < 8; ++j) bb[j] = Bs[kk][tn + j];
            #pragma unroll
            for (int i = 0; i < 8; ++i)
                #pragma unroll
                for (int j = 0; j < 8; ++j)
                    acc[i][j] = fmaf(am[i], bb[j], acc[i][j]);
        }
        __syncthreads();
    }

    #pragma unroll
    for (int i = 0; i < 8; ++i) {
        float* cp = Cm + (size_t)(bm + tm + i) * N + bn + tn;
        *(float4*)(cp + 0) = make_float4(acc[i][0], acc[i][1], acc[i][2], acc[i][3]);
        *(float4*)(cp + 4) = make_float4(acc[i][4], acc[i][5], acc[i][6], acc[i][7]);
    }
}

// ---------------------------------------------------------------------------
// Flash-attention with ALiBi (+slope*|i-j| == +slope*(i-j) under causal mask).
// One block per (b,h, 64-row Q tile). 256 threads = 16x16 grid, 4x4 micro.
// KV tiles of 64; causal tile skipping (jt <= qt). Online softmax.
// ---------------------------------------------------------------------------
#define SSTR 65   // smem row stride (pad to break bank conflicts)

__global__ __launch_bounds__(256) void attn_kernel(
    const float* __restrict__ qkv, float* __restrict__ out)
{
    extern __shared__ float sh[];
    float* Qs = sh;                   // [64][65]
    float* Ks = Qs + 64 * SSTR;       // [64][65]
    float* Vs = Ks + 64 * SSTR;       // [64][65]
    float* Ps = Vs + 64 * SSTR;       // [64][65]

    const int qt = blockIdx.x;        // 0..31
    const int bh = blockIdx.y;        // 0..31
    const int b = bh >> 4, h = bh & 15;
    const int tid = threadIdx.x;
    const int tx = tid & 15, ty = tid >> 4;

    const float slope = exp2f(-0.5f * (float)(h + 1));  // 1/2^(8*(h+1)/H)
    const float scale = 0.125f;                          // 1/sqrt(64)

    const float* qb = qkv + (size_t)b * T_ * 3 * C_ + h * D_;
    const float* kb = qb + C_;
    const float* vb = qb + 2 * C_;

    // Load Q tile [64][64] (visible after first __syncthreads below)
    {
        const int r = tid >> 4;
        const int c = (tid & 15) * 4;
        #pragma unroll
        for (int it = 0; it < 4; ++it) {
            const int row = r + it * 16;
            const float4 v = *(const float4*)(qb + (size_t)(qt * 64 + row) * (3 * C_) + c);
            float* dst = &Qs[row * SSTR + c];
            dst[0] = v.x; dst[1] = v.y; dst[2] = v.z; dst[3] = v.w;
        }
    }

    float o[4][4];
    float m[4], l[4];
    #pragma unroll
    for (int i = 0; i < 4; ++i) {
        m[i] = -INFINITY; l[i] = 0.f;
        #pragma unroll
        for (int j = 0; j < 4; ++j) o[i][j] = 0.f;
    }

    for (int jt = 0; jt <= qt; ++jt) {
        __syncthreads();  // prior-tile PV reads of Ks/Vs done before overwrite
        // Load K,V tiles
        {
            const int r = tid >> 4;
            const int c = (tid & 15) * 4;
            #pragma unroll
            for (int it = 0; it < 4; ++it) {
                const int row = r + it * 16;
                const size_t goff = (size_t)(jt * 64 + row) * (3 * C_) + c;
                const float4 kv4 = *(const float4*)(kb + goff);
                const float4 vv4 = *(const float4*)(vb + goff);
                float* kd = &Ks[row * SSTR + c];
                kd[0] = kv4.x; kd[1] = kv4.y; kd[2] = kv4.z; kd[3] = kv4.w;
                float* vd = &Vs[row * SSTR + c];
                vd[0] = vv4.x; vd[1] = vv4.y; vd[2] = vv4.z; vd[3] = vv4.w;
            }
        }
        __syncthreads();

        // S = Q @ K^T   (4x4 per thread)
        float s[4][4];
        #pragma unroll
        for (int i = 0; i < 4; ++i)
            #pragma unroll
            for (int j = 0; j < 4; ++j) s[i][j] = 0.f;

        #pragma unroll 4
        for (int d = 0; d < 64; ++d) {
            float qr[4], kr[4];
            #pragma unroll
            for (int i = 0; i < 4; ++i) qr[i] = Qs[(ty * 4 + i) * SSTR + d];
            #pragma unroll
            for (int j = 0; j < 4; ++j) kr[j] = Ks[(tx * 4 + j) * SSTR + d];
            #pragma unroll
            for (int i = 0; i < 4; ++i)
                #pragma unroll
                for (int j = 0; j < 4; ++j)
                    s[i][j] = fmaf(qr[i], kr[j], s[i][j]);
        }

        // scale + ALiBi bias + causal mask (only diagonal tile can mask)
        const bool diag = (jt == qt);
        #pragma unroll
        for (int i = 0; i < 4; ++i) {
            const int gi = qt * 64 + ty * 4 + i;
            #pragma unroll
            for (int j = 0; j < 4; ++j) {
                const int gj = jt * 64 + tx * 4 + j;
                float sv = s[i][j] * scale + slope * (float)(gi - gj);
                if (diag && gj > gi) sv = -INFINITY;
                s[i][j] = sv;
            }
        }

        // online softmax: rows owned by 16 lanes (same ty) within a warp half
        #pragma unroll
        for (int i = 0; i < 4; ++i) {
            float rm = fmaxf(fmaxf(s[i][0], s[i][1]), fmaxf(s[i][2], s[i][3]));
            #pragma unroll
            for (int off = 8; off >= 1; off >>= 1)
                rm = fmaxf(rm, __shfl_xor_sync(0xffffffffu, rm, off));
            const float mnew = fmaxf(m[i], rm);
            const float corr = __expf(m[i] - mnew);
            m[i] = mnew;
            float rsum = 0.f;
            #pragma unroll
            for (int j = 0; j < 4; ++j) {
                const float p = __expf(s[i][j] - mnew);
                Ps[(ty * 4 + i) * SSTR + tx * 4 + j] = p;
                rsum += p;
            }
            #pragma unroll
            for (int off = 8; off >= 1; off >>= 1)
                rsum += __shfl_xor_sync(0xffffffffu, rsum, off);
            l[i] = l[i] * corr + rsum;
            #pragma unroll
            for (int j = 0; j < 4; ++j) o[i][j] *= corr;
        }
        __syncthreads();  // Ps fully written

        // O += P @ V
        #pragma unroll 4
        for (int kk = 0; kk < 64; ++kk) {
            float pr[4], vr[4];
            #pragma unroll
            for (int i = 0; i < 4; ++i) pr[i] = Ps[(ty * 4 + i) * SSTR + kk];
            #pragma unroll
            for (int j = 0; j < 4; ++j) vr[j] = Vs[kk * SSTR + tx * 4 + j];
            #pragma unroll
            for (int i = 0; i < 4; ++i)
                #pragma unroll
                for (int j = 0; j < 4; ++j)
                    o[i][j] = fmaf(pr[i], vr[j], o[i][j]);
        }
    }

    // epilogue: normalize, write to [B,T,C] (heads re-interleaved)
    #pragma unroll
    for (int i = 0; i < 4; ++i) {
        const float linv = 1.f / l[i];
        float* op = out + ((size_t)b * T_ + qt * 64 + ty * 4 + i) * C_ + h * D_ + tx * 4;
        op[0] = o[i][0] * linv;
        op[1] = o[i][1] * linv;
        op[2] = o[i][2] * linv;
        op[3] = o[i][3] * linv;
    }
}

// ---------------------------------------------------------------------------
extern "C" void kernel_launch(void* const* d_in, const int* in_sizes, int n_in,
                              void* d_out, int out_size)
{
    const float* x      = (const float*)d_in[0];  // [B,T,C]
    const float* w_qkv  = (const float*)d_in[1];  // [C,3C]
    const float* w_proj = (const float*)d_in[2];  // [C,C]
    float* out = (float*)d_out;                   // [B,T,C]

    float *qkv, *att;
    cudaGetSymbolAddress((void**)&qkv, g_qkv);
    cudaGetSymbolAddress((void**)&att, g_att);

    const int smem_attn = 4 * 64 * SSTR * sizeof(float);  // 66560 B
    cudaFuncSetAttribute(attn_kernel, cudaFuncAttributeMaxDynamicSharedMemorySize, smem_attn);

    const int M = B_ * T_;  // 4096

    // 1) qkv = x @ w_qkv   [4096,1024]x[1024,3072]
    sgemm128<<<dim3((3 * C_) / 128, M / 128), 256>>>(x, w_qkv, qkv, M, 3 * C_, C_);

    // 2) attention -> att [B,T,C]
    attn_kernel<<<dim3(T_ / 64, B_ * H_), 256, smem_attn>>>(qkv, att);

    // 3) out = att @ w_proj [4096,1024]x[1024,1024]
    sgemm128<<<dim3(C_ / 128, M / 128), 256>>>(att, w_proj, out, M, C_, C_);
}

// round 3
// speedup vs baseline: 1.3310x; 1.3310x over previous
#include <cuda_runtime.h>
#include <cuda_bf16.h>
#include <math.h>
#include <stdint.h>

#define B_ 2
#define T_ 2048
#define C_ 1024
#define H_ 16
#define D_ 64

// Scratch (allocation-free rule: __device__ globals)
__device__ float g_qkv[(size_t)B_ * T_ * 3 * C_];   // [B,T,3C]
__device__ float g_att[(size_t)B_ * T_ * C_];       // [B,T,C]

// ---------------------------------------------------------------------------
// Warp-level MMA helpers (base-target instructions: sm_80 mma.sync, ldmatrix)
// ---------------------------------------------------------------------------
__device__ __forceinline__ uint32_t smem_u32(const void* p) {
    uint32_t a;
    asm("{ .reg .u64 t; cvta.to.shared.u64 t, %1; cvt.u32.u64 %0, t; }"
        : "=r"(a) : "l"(p));
    return a;
}
__device__ __forceinline__ void ldsm_x4(uint32_t* r, uint32_t addr) {
    asm volatile("ldmatrix.sync.aligned.m8n8.x4.shared.b16 {%0,%1,%2,%3}, [%4];"
                 : "=r"(r[0]), "=r"(r[1]), "=r"(r[2]), "=r"(r[3]) : "r"(addr));
}
__device__ __forceinline__ void mma16816(float* d, const uint32_t* a,
                                         uint32_t b0, uint32_t b1) {
    asm volatile(
        "mma.sync.aligned.m16n8k16.row.col.f32.bf16.bf16.f32 "
        "{%0,%1,%2,%3}, {%4,%5,%6,%7}, {%8,%9}, {%0,%1,%2,%3};"
        : "+f"(d[0]), "+f"(d[1]), "+f"(d[2]), "+f"(d[3])
        : "r"(a[0]), "r"(a[1]), "r"(a[2]), "r"(a[3]), "r"(b0), "r"(b1));
}
__device__ __forceinline__ uint32_t pkbf2(__nv_bfloat16 a, __nv_bfloat16 b) {
    __nv_bfloat162 t(a, b);
    return *reinterpret_cast<uint32_t*>(&t);
}
// split 8 floats -> 4 hi-pairs + 4 lo-pairs (bf16x2)
__device__ __forceinline__ void split8(const float* f, uint32_t* hi, uint32_t* lo) {
    #pragma unroll
    for (int j = 0; j < 4; ++j) {
        const __nv_bfloat16 h0 = __float2bfloat16(f[2 * j]);
        const __nv_bfloat16 h1 = __float2bfloat16(f[2 * j + 1]);
        const __nv_bfloat16 l0 = __float2bfloat16(f[2 * j]     - __bfloat162float(h0));
        const __nv_bfloat16 l1 = __float2bfloat16(f[2 * j + 1] - __bfloat162float(h1));
        hi[j] = pkbf2(h0, h1);
        lo[j] = pkbf2(l0, l1);
    }
}

// ---------------------------------------------------------------------------
// bf16-split GEMM on mma.sync: C[M,N] = A[M,K] @ B[K,N], fp32 in/out, row-major
// CTA tile 128x128, BK=32, 256 threads (8 warps, 4x2 grid, warp tile 32x64).
// D = Ah*Bh + Ah*Bl + Al*Bh, fp32 accumulation in registers.
// Requires M%128==0, N%128==0, K%32==0.
// ---------------------------------------------------------------------------
#define ASTR 40                       // bf16 elems per smem row (80B, 16B-aligned)
#define TILE_B (128 * ASTR * 2)       // 10240 bytes per tile
#define OFF_AH 0
#define OFF_AL (TILE_B)
#define OFF_BH (2 * TILE_B)
#define OFF_BL (3 * TILE_B)
#define GEMM_SMEM (4 * TILE_B)        // 40960 B

__global__ __launch_bounds__(256) void gemm_mma(
    const float* __restrict__ A, const float* __restrict__ Bm,
    float* __restrict__ Cm, int M, int N, int K)
{
    extern __shared__ __align__(128) char smem[];
    const uint32_t sb = smem_u32(smem);

    const int tid = threadIdx.x;
    const int wid = tid >> 5, lane = tid & 31;
    const int bm = blockIdx.y * 128, bn = blockIdx.x * 128;
    const int wm = (wid >> 1) * 32;           // warp M offset in tile
    const int wn = (wid & 1) * 64;            // warp N offset in tile

    // ---- loader indices
    // A: thread handles row (tid&127), cols [half*16, half*16+16) of the chunk
    const int l_row  = tid & 127;
    const int l_half = tid >> 7;              // 0 or 1
    const float* Ap = A + (size_t)(bm + l_row) * K + l_half * 16;
    // B: thread handles column (bn + l_row), k in [half*16, half*16+16)
    const float* Bp = Bm + (size_t)(l_half * 16) * N + bn + l_row;
    // smem store address (same for A and Bt layouts)
    const uint32_t st_off = (uint32_t)l_row * (ASTR * 2) + l_half * 32;

    // ---- fragment ldmatrix addresses
    // A frag (m16k16 at (wm + mi*16, k0)): row = wm + mi*16 + (lane&15), col = k0 + (lane>>4)*8
    const int a_r = wm + (lane & 15);
    const int a_c = (lane >> 4) * 8;
    // B frag x4 (n-tiles wn+j*16, wn+j*16+8; k0): see lane decomposition
    const int b_ln  = lane & 7;
    const int b_sel = lane >> 3;              // 0..3
    const int b_r   = wn + (b_sel >> 1) * 8 + b_ln;
    const int b_c   = (b_sel & 1) * 8;

    float acc[2][8][4];
    #pragma unroll
    for (int mi = 0; mi < 2; ++mi)
        #pragma unroll
        for (int ni = 0; ni < 8; ++ni)
            #pragma unroll
            for (int q = 0; q < 4; ++q) acc[mi][ni][q] = 0.f;

    // ---- prefetch chunk 0
    float fa[16], fb[16];
    {
        #pragma unroll
        for (int q = 0; q < 4; ++q)
            *(float4*)(fa + q * 4) = *(const float4*)(Ap + q * 4);
        #pragma unroll
        for (int kk = 0; kk < 16; ++kk)
            fb[kk] = Bp[(size_t)kk * N];
    }

    const int nchunks = K / 32;
    for (int ch = 0; ch < nchunks; ++ch) {
        // store prefetched chunk to smem (with hi/lo split)
        {
            uint32_t hi[4], lo[4];
            split8(fa, hi, lo);
            *(uint4*)(smem + OFF_AH + st_off)      = make_uint4(hi[0], hi[1], hi[2], hi[3]);
            *(uint4*)(smem + OFF_AL + st_off)      = make_uint4(lo[0], lo[1], lo[2], lo[3]);
            split8(fa + 8, hi, lo);
            *(uint4*)(smem + OFF_AH + st_off + 16) = make_uint4(hi[0], hi[1], hi[2], hi[3]);
            *(uint4*)(smem + OFF_AL + st_off + 16) = make_uint4(lo[0], lo[1], lo[2], lo[3]);
            split8(fb, hi, lo);
            *(uint4*)(smem + OFF_BH + st_off)      = make_uint4(hi[0], hi[1], hi[2], hi[3]);
            *(uint4*)(smem + OFF_BL + st_off)      = make_uint4(lo[0], lo[1], lo[2], lo[3]);
            split8(fb + 8, hi, lo);
            *(uint4*)(smem + OFF_BH + st_off + 16) = make_uint4(hi[0], hi[1], hi[2], hi[3]);
            *(uint4*)(smem + OFF_BL + st_off + 16) = make_uint4(lo[0], lo[1], lo[2], lo[3]);
        }
        __syncthreads();

        // prefetch next chunk
        if (ch + 1 < nchunks) {
            const float* Apn = Ap + (ch + 1) * 32;
            const float* Bpn = Bp + (size_t)(ch + 1) * 32 * N;
            #pragma unroll
            for (int q = 0; q < 4; ++q)
                *(float4*)(fa + q * 4) = *(const float4*)(Apn + q * 4);
            #pragma unroll
            for (int kk = 0; kk < 16; ++kk)
                fb[kk] = Bpn[(size_t)kk * N];
        }

        // compute: 2 k16-steps
        #pragma unroll
        for (int ks = 0; ks < 2; ++ks) {
            const int k0 = ks * 16;
            uint32_t aH[2][4], aL[2][4];
            #pragma unroll
            for (int mi = 0; mi < 2; ++mi) {
                const uint32_t ao = (uint32_t)(a_r + mi * 16) * (ASTR * 2) + (k0 + a_c) * 2;
                ldsm_x4(aH[mi], sb + OFF_AH + ao);
                ldsm_x4(aL[mi], sb + OFF_AL + ao);
            }
            #pragma unroll
            for (int j = 0; j < 4; ++j) {       // each j covers n-tiles 2j, 2j+1
                const uint32_t bo = (uint32_t)(b_r + j * 16) * (ASTR * 2) + (k0 + b_c) * 2;
                uint32_t bH[4], bL[4];
                ldsm_x4(bH, sb + OFF_BH + bo);
                ldsm_x4(bL, sb + OFF_BL + bo);
                #pragma unroll
                for (int mi = 0; mi < 2; ++mi) {
                    mma16816(acc[mi][2 * j],     aH[mi], bH[0], bH[1]);
                    mma16816(acc[mi][2 * j],     aH[mi], bL[0], bL[1]);
                    mma16816(acc[mi][2 * j],     aL[mi], bH[0], bH[1]);
                    mma16816(acc[mi][2 * j + 1], aH[mi], bH[2], bH[3]);
                    mma16816(acc[mi][2 * j + 1], aH[mi], bL[2], bL[3]);
                    mma16816(acc[mi][2 * j + 1], aL[mi], bH[2], bH[3]);
                }
            }
        }
        __syncthreads();
    }

    // ---- epilogue: direct fp32 stores
    const int g = lane >> 2, cpair = (lane & 3) * 2;
    #pragma unroll
    for (int mi = 0; mi < 2; ++mi) {
        #pragma unroll
        for (int ni = 0; ni < 8; ++ni) {
            float* p0 = Cm + (size_t)(bm + wm + mi * 16 + g)     * N + bn + wn + ni * 8 + cpair;
            float* p1 = Cm + (size_t)(bm + wm + mi * 16 + g + 8) * N + bn + wn + ni * 8 + cpair;
            *(float2*)p0 = make_float2(acc[mi][ni][0], acc[mi][ni][1]);
            *(float2*)p1 = make_float2(acc[mi][ni][2], acc[mi][ni][3]);
        }
    }
}

// ---------------------------------------------------------------------------
// Flash-attention with ALiBi (unchanged from R1)
// ---------------------------------------------------------------------------
#define SSTR 65

__global__ __launch_bounds__(256) void attn_kernel(
    const float* __restrict__ qkv, float* __restrict__ out)
{
    extern __shared__ float sh[];
    float* Qs = sh;
    float* Ks = Qs + 64 * SSTR;
    float* Vs = Ks + 64 * SSTR;
    float* Ps = Vs + 64 * SSTR;

    const int qt = blockIdx.x;
    const int bh = blockIdx.y;
    const int b = bh >> 4, h = bh & 15;
    const int tid = threadIdx.x;
    const int tx = tid & 15, ty = tid >> 4;

    const float slope = exp2f(-0.5f * (float)(h + 1));
    const float scale = 0.125f;

    const float* qb = qkv + (size_t)b * T_ * 3 * C_ + h * D_;
    const float* kb = qb + C_;
    const float* vb = qb + 2 * C_;

    {
        const int r = tid >> 4;
        const int c = (tid & 15) * 4;
        #pragma unroll
        for (int it = 0; it < 4; ++it) {
            const int row = r + it * 16;
            const float4 v = *(const float4*)(qb + (size_t)(qt * 64 + row) * (3 * C_) + c);
            float* dst = &Qs[row * SSTR + c];
            dst[0] = v.x; dst[1] = v.y; dst[2] = v.z; dst[3] = v.w;
        }
    }

    float o[4][4];
    float m[4], l[4];
    #pragma unroll
    for (int i = 0; i < 4; ++i) {
        m[i] = -INFINITY; l[i] = 0.f;
        #pragma unroll
        for (int j = 0; j < 4; ++j) o[i][j] = 0.f;
    }

    for (int jt = 0; jt <= qt; ++jt) {
        __syncthreads();
        {
            const int r = tid >> 4;
            const int c = (tid & 15) * 4;
            #pragma unroll
            for (int it = 0; it < 4; ++it) {
                const int row = r + it * 16;
                const size_t goff = (size_t)(jt * 64 + row) * (3 * C_) + c;
                const float4 kv4 = *(const float4*)(kb + goff);
                const float4 vv4 = *(const float4*)(vb + goff);
                float* kd = &Ks[row * SSTR + c];
                kd[0] = kv4.x; kd[1] = kv4.y; kd[2] = kv4.z; kd[3] = kv4.w;
                float* vd = &Vs[row * SSTR + c];
                vd[0] = vv4.x; vd[1] = vv4.y; vd[2] = vv4.z; vd[3] = vv4.w;
            }
        }
        __syncthreads();

        float s[4][4];
        #pragma unroll
        for (int i = 0; i < 4; ++i)
            #pragma unroll
            for (int j = 0; j < 4; ++j) s[i][j] = 0.f;

        #pragma unroll 4
        for (int d = 0; d < 64; ++d) {
            float qr[4], kr[4];
            #pragma unroll
            for (int i = 0; i < 4; ++i) qr[i] = Qs[(ty * 4 + i) * SSTR + d];
            #pragma unroll
            for (int j = 0; j < 4; ++j) kr[j] = Ks[(tx * 4 + j) * SSTR + d];
            #pragma unroll
            for (int i = 0; i < 4; ++i)
                #pragma unroll
                for (int j = 0; j < 4; ++j)
                    s[i][j] = fmaf(qr[i], kr[j], s[i][j]);
        }

        const bool diag = (jt == qt);
        #pragma unroll
        for (int i = 0; i < 4; ++i) {
            const int gi = qt * 64 + ty * 4 + i;
            #pragma unroll
            for (int j = 0; j < 4; ++j) {
                const int gj = jt * 64 + tx * 4 + j;
                float sv = s[i][j] * scale + slope * (float)(gi - gj);
                if (diag && gj > gi) sv = -INFINITY;
                s[i][j] = sv;
            }
        }

        #pragma unroll
        for (int i = 0; i < 4; ++i) {
            float rm = fmaxf(fmaxf(s[i][0], s[i][1]), fmaxf(s[i][2], s[i][3]));
            #pragma unroll
            for (int off = 8; off >= 1; off >>= 1)
                rm = fmaxf(rm, __shfl_xor_sync(0xffffffffu, rm, off));
            const float mnew = fmaxf(m[i], rm);
            const float corr = __expf(m[i] - mnew);
            m[i] = mnew;
            float rsum = 0.f;
            #pragma unroll
            for (int j = 0; j < 4; ++j) {
                const float p = __expf(s[i][j] - mnew);
                Ps[(ty * 4 + i) * SSTR + tx * 4 + j] = p;
                rsum += p;
            }
            #pragma unroll
            for (int off = 8; off >= 1; off >>= 1)
                rsum += __shfl_xor_sync(0xffffffffu, rsum, off);
            l[i] = l[i] * corr + rsum;
            #pragma unroll
            for (int j = 0; j < 4; ++j) o[i][j] *= corr;
        }
        __syncthreads();

        #pragma unroll 4
        for (int kk = 0; kk < 64; ++kk) {
            float pr[4], vr[4];
            #pragma unroll
            for (int i = 0; i < 4; ++i) pr[i] = Ps[(ty * 4 + i) * SSTR + kk];
            #pragma unroll
            for (int j = 0; j < 4; ++j) vr[j] = Vs[kk * SSTR + tx * 4 + j];
            #pragma unroll
            for (int i = 0; i < 4; ++i)
                #pragma unroll
                for (int j = 0; j < 4; ++j)
                    o[i][j] = fmaf(pr[i], vr[j], o[i][j]);
        }
    }

    #pragma unroll
    for (int i = 0; i < 4; ++i) {
        const float linv = 1.f / l[i];
        float* op = out + ((size_t)b * T_ + qt * 64 + ty * 4 + i) * C_ + h * D_ + tx * 4;
        op[0] = o[i][0] * linv;
        op[1] = o[i][1] * linv;
        op[2] = o[i][2] * linv;
        op[3] = o[i][3] * linv;
    }
}

// ---------------------------------------------------------------------------
extern "C" void kernel_launch(void* const* d_in, const int* in_sizes, int n_in,
                              void* d_out, int out_size)
{
    const float* x      = (const float*)d_in[0];  // [B,T,C]
    const float* w_qkv  = (const float*)d_in[1];  // [C,3C]
    const float* w_proj = (const float*)d_in[2];  // [C,C]
    float* out = (float*)d_out;                   // [B,T,C]

    float *qkv, *att;
    cudaGetSymbolAddress((void**)&qkv, g_qkv);
    cudaGetSymbolAddress((void**)&att, g_att);

    const int smem_attn = 4 * 64 * SSTR * sizeof(float);
    cudaFuncSetAttribute(attn_kernel, cudaFuncAttributeMaxDynamicSharedMemorySize, smem_attn);

    const int M = B_ * T_;  // 4096

    // 1) qkv = x @ w_qkv   [4096,1024]x[1024,3072]
    gemm_mma<<<dim3((3 * C_) / 128, M / 128), 256, GEMM_SMEM>>>(x, w_qkv, qkv, M, 3 * C_, C_);

    // 2) attention -> att [B,T,C]
    attn_kernel<<<dim3(T_ / 64, B_ * H_), 256, smem_attn>>>(qkv, att);

    // 3) out = att @ w_proj [4096,1024]x[1024,1024]
    gemm_mma<<<dim3(C_ / 128, M / 128), 256, GEMM_SMEM>>>(att, w_proj, out, M, C_, C_);
}

// round 4
// speedup vs baseline: 2.2021x; 1.6545x over previous
#include <cuda_runtime.h>
#include <cuda_bf16.h>
#include <math.h>
#include <stdint.h>

#define B_ 2
#define T_ 2048
#define C_ 1024
#define H_ 16
#define D_ 64

// Scratch (allocation-free rule: __device__ globals)
__device__ float g_qkv[(size_t)B_ * T_ * 3 * C_];   // [B,T,3C]
__device__ float g_att[(size_t)B_ * T_ * C_];       // [B,T,C]

// ---------------------------------------------------------------------------
// Warp-level MMA helpers (base-target instructions: sm_80 mma.sync, ldmatrix)
// ---------------------------------------------------------------------------
__device__ __forceinline__ uint32_t smem_u32(const void* p) {
    uint32_t a;
    asm("{ .reg .u64 t; cvta.to.shared.u64 t, %1; cvt.u32.u64 %0, t; }"
        : "=r"(a) : "l"(p));
    return a;
}
__device__ __forceinline__ void ldsm_x4(uint32_t* r, uint32_t addr) {
    asm volatile("ldmatrix.sync.aligned.m8n8.x4.shared.b16 {%0,%1,%2,%3}, [%4];"
                 : "=r"(r[0]), "=r"(r[1]), "=r"(r[2]), "=r"(r[3]) : "r"(addr));
}
__device__ __forceinline__ void ldsm_x4_t(uint32_t* r, uint32_t addr) {
    asm volatile("ldmatrix.sync.aligned.m8n8.x4.trans.shared.b16 {%0,%1,%2,%3}, [%4];"
                 : "=r"(r[0]), "=r"(r[1]), "=r"(r[2]), "=r"(r[3]) : "r"(addr));
}
__device__ __forceinline__ void mma16816(float* d, const uint32_t* a,
                                         uint32_t b0, uint32_t b1) {
    asm volatile(
        "mma.sync.aligned.m16n8k16.row.col.f32.bf16.bf16.f32 "
        "{%0,%1,%2,%3}, {%4,%5,%6,%7}, {%8,%9}, {%0,%1,%2,%3};"
        : "+f"(d[0]), "+f"(d[1]), "+f"(d[2]), "+f"(d[3])
        : "r"(a[0]), "r"(a[1]), "r"(a[2]), "r"(a[3]), "r"(b0), "r"(b1));
}
__device__ __forceinline__ uint32_t pkbf2(__nv_bfloat16 a, __nv_bfloat16 b) {
    __nv_bfloat162 t(a, b);
    return *reinterpret_cast<uint32_t*>(&t);
}
// split two floats into hi/lo bf16x2 regs
__device__ __forceinline__ void split2(float a, float b, uint32_t& hi, uint32_t& lo) {
    const __nv_bfloat16 ha = __float2bfloat16(a);
    const __nv_bfloat16 hb = __float2bfloat16(b);
    hi = pkbf2(ha, hb);
    lo = pkbf2(__float2bfloat16(a - __bfloat162float(ha)),
               __float2bfloat16(b - __bfloat162float(hb)));
}
// split 8 floats -> 4 hi-pairs + 4 lo-pairs (bf16x2)
__device__ __forceinline__ void split8(const float* f, uint32_t* hi, uint32_t* lo) {
    #pragma unroll
    for (int j = 0; j < 4; ++j) split2(f[2 * j], f[2 * j + 1], hi[j], lo[j]);
}

// ---------------------------------------------------------------------------
// bf16-split GEMM on mma.sync: C[M,N] = A[M,K] @ B[K,N], fp32 in/out, row-major
// CTA tile 128x128, BK=32, 256 threads (8 warps, 4x2 grid, warp tile 32x64).
// ---------------------------------------------------------------------------
#define ASTR 40
#define TILE_B (128 * ASTR * 2)
#define OFF_AH 0
#define OFF_AL (TILE_B)
#define OFF_BH (2 * TILE_B)
#define OFF_BL (3 * TILE_B)
#define GEMM_SMEM (4 * TILE_B)

__global__ __launch_bounds__(256, 2) void gemm_mma(
    const float* __restrict__ A, const float* __restrict__ Bm,
    float* __restrict__ Cm, int M, int N, int K)
{
    extern __shared__ __align__(128) char smem[];
    const uint32_t sb = smem_u32(smem);

    const int tid = threadIdx.x;
    const int wid = tid >> 5, lane = tid & 31;
    const int bm = blockIdx.y * 128, bn = blockIdx.x * 128;
    const int wm = (wid >> 1) * 32;
    const int wn = (wid & 1) * 64;

    const int l_row  = tid & 127;
    const int l_half = tid >> 7;
    const float* Ap = A + (size_t)(bm + l_row) * K + l_half * 16;
    const float* Bp = Bm + (size_t)(l_half * 16) * N + bn + l_row;
    const uint32_t st_off = (uint32_t)l_row * (ASTR * 2) + l_half * 32;

    const int a_r = wm + (lane & 15);
    const int a_c = (lane >> 4) * 8;
    const int b_ln  = lane & 7;
    const int b_sel = lane >> 3;
    const int b_r   = wn + (b_sel >> 1) * 8 + b_ln;
    const int b_c   = (b_sel & 1) * 8;

    float acc[2][8][4];
    #pragma unroll
    for (int mi = 0; mi < 2; ++mi)
        #pragma unroll
        for (int ni = 0; ni < 8; ++ni)
            #pragma unroll
            for (int q = 0; q < 4; ++q) acc[mi][ni][q] = 0.f;

    float fa[16], fb[16];
    #pragma unroll
    for (int q = 0; q < 4; ++q)
        *(float4*)(fa + q * 4) = *(const float4*)(Ap + q * 4);
    #pragma unroll
    for (int kk = 0; kk < 16; ++kk)
        fb[kk] = Bp[(size_t)kk * N];

    const int nchunks = K / 32;
    for (int ch = 0; ch < nchunks; ++ch) {
        {
            uint32_t hi[4], lo[4];
            split8(fa, hi, lo);
            *(uint4*)(smem + OFF_AH + st_off)      = make_uint4(hi[0], hi[1], hi[2], hi[3]);
            *(uint4*)(smem + OFF_AL + st_off)      = make_uint4(lo[0], lo[1], lo[2], lo[3]);
            split8(fa + 8, hi, lo);
            *(uint4*)(smem + OFF_AH + st_off + 16) = make_uint4(hi[0], hi[1], hi[2], hi[3]);
            *(uint4*)(smem + OFF_AL + st_off + 16) = make_uint4(lo[0], lo[1], lo[2], lo[3]);
            split8(fb, hi, lo);
            *(uint4*)(smem + OFF_BH + st_off)      = make_uint4(hi[0], hi[1], hi[2], hi[3]);
            *(uint4*)(smem + OFF_BL + st_off)      = make_uint4(lo[0], lo[1], lo[2], lo[3]);
            split8(fb + 8, hi, lo);
            *(uint4*)(smem + OFF_BH + st_off + 16) = make_uint4(hi[0], hi[1], hi[2], hi[3]);
            *(uint4*)(smem + OFF_BL + st_off + 16) = make_uint4(lo[0], lo[1], lo[2], lo[3]);
        }
        __syncthreads();

        if (ch + 1 < nchunks) {
            const float* Apn = Ap + (ch + 1) * 32;
            const float* Bpn = Bp + (size_t)(ch + 1) * 32 * N;
            #pragma unroll
            for (int q = 0; q < 4; ++q)
                *(float4*)(fa + q * 4) = *(const float4*)(Apn + q * 4);
            #pragma unroll
            for (int kk = 0; kk < 16; ++kk)
                fb[kk] = Bpn[(size_t)kk * N];
        }

        #pragma unroll
        for (int ks = 0; ks < 2; ++ks) {
            const int k0 = ks * 16;
            uint32_t aH[2][4], aL[2][4];
            #pragma unroll
            for (int mi = 0; mi < 2; ++mi) {
                const uint32_t ao = (uint32_t)(a_r + mi * 16) * (ASTR * 2) + (k0 + a_c) * 2;
                ldsm_x4(aH[mi], sb + OFF_AH + ao);
                ldsm_x4(aL[mi], sb + OFF_AL + ao);
            }
            #pragma unroll
            for (int j = 0; j < 4; ++j) {
                const uint32_t bo = (uint32_t)(b_r + j * 16) * (ASTR * 2) + (k0 + b_c) * 2;
                uint32_t bH[4], bL[4];
                ldsm_x4(bH, sb + OFF_BH + bo);
                ldsm_x4(bL, sb + OFF_BL + bo);
                #pragma unroll
                for (int mi = 0; mi < 2; ++mi) {
                    mma16816(acc[mi][2 * j],     aH[mi], bH[0], bH[1]);
                    mma16816(acc[mi][2 * j],     aH[mi], bL[0], bL[1]);
                    mma16816(acc[mi][2 * j],     aL[mi], bH[0], bH[1]);
                    mma16816(acc[mi][2 * j + 1], aH[mi], bH[2], bH[3]);
                    mma16816(acc[mi][2 * j + 1], aH[mi], bL[2], bL[3]);
                    mma16816(acc[mi][2 * j + 1], aL[mi], bH[2], bH[3]);
                }
            }
        }
        __syncthreads();
    }

    const int g = lane >> 2, cpair = (lane & 3) * 2;
    #pragma unroll
    for (int mi = 0; mi < 2; ++mi) {
        #pragma unroll
        for (int ni = 0; ni < 8; ++ni) {
            float* p0 = Cm + (size_t)(bm + wm + mi * 16 + g)     * N + bn + wn + ni * 8 + cpair;
            float* p1 = Cm + (size_t)(bm + wm + mi * 16 + g + 8) * N + bn + wn + ni * 8 + cpair;
            *(float2*)p0 = make_float2(acc[mi][ni][0], acc[mi][ni][1]);
            *(float2*)p1 = make_float2(acc[mi][ni][2], acc[mi][ni][3]);
        }
    }
}

// ---------------------------------------------------------------------------
// Flash-attention on mma.sync with bf16-split numerics + ALiBi.
// CTA: 128 Q rows x one (b,h). 256 thr = 8 warps; warp w owns rows [w*16, w*16+16)
// across all 64 KV cols of a tile -> softmax is warp-local (quad shfl).
// S = Qh*Kh + Qh*Kl + Ql*Kh ; O += Ph*Vh + Ph*Vl + Pl*Vh (fp32 accum).
// P A-frags reused straight from S accumulators; V via ldmatrix.trans.
// ---------------------------------------------------------------------------
#define KSTR 144                      // bytes per smem row (72 bf16)
#define AKH 0
#define AKL (64 * KSTR)
#define AVH (2 * 64 * KSTR)
#define AVL (3 * 64 * KSTR)
#define ATTN_SMEM (4 * 64 * KSTR)     // 36864 B

__global__ __launch_bounds__(256) void attn_mma(
    const float* __restrict__ qkv, float* __restrict__ out)
{
    extern __shared__ __align__(128) char smem[];
    const uint32_t sb = smem_u32(smem);

    const int qt = blockIdx.x;        // 0..15 (128 rows each)
    const int bh = blockIdx.y;        // 0..31
    const int b = bh >> 4, h = bh & 15;
    const int tid = threadIdx.x;
    const int wid = tid >> 5, lane = tid & 31;
    const int g = lane >> 2, c = lane & 3;
    const int wq = wid * 16;

    const float slope = exp2f(-0.5f * (float)(h + 1));

    const float* qb = qkv + (size_t)b * T_ * 3 * C_ + h * D_;
    const float* kb = qb + C_;
    const float* vb = qb + 2 * C_;

    // ---- Q fragments straight from gmem (scale folded in pre-split)
    uint32_t qh[4][4], ql[4][4];
    {
        const float* q0 = qb + (size_t)(qt * 128 + wq + g) * (3 * C_);
        const float* q8 = q0 + (size_t)8 * 3 * C_;
        #pragma unroll
        for (int s = 0; s < 4; ++s) {
            const int k0 = s * 16 + 2 * c;
            const float2 x0 = *(const float2*)(q0 + k0);
            const float2 x1 = *(const float2*)(q8 + k0);
            const float2 x2 = *(const float2*)(q0 + k0 + 8);
            const float2 x3 = *(const float2*)(q8 + k0 + 8);
            split2(x0.x * 0.125f, x0.y * 0.125f, qh[s][0], ql[s][0]);
            split2(x1.x * 0.125f, x1.y * 0.125f, qh[s][1], ql[s][1]);
            split2(x2.x * 0.125f, x2.y * 0.125f, qh[s][2], ql[s][2]);
            split2(x3.x * 0.125f, x3.y * 0.125f, qh[s][3], ql[s][3]);
        }
    }

    // K frag (non-trans) address pieces: row = base_n + (lane>>4)*8 + (lane&7),
    // col = k0 + ((lane>>3)&1)*8
    const uint32_t k_row = (uint32_t)((lane >> 4) * 8 + (lane & 7));
    const uint32_t k_colb = (uint32_t)(((lane >> 3) & 1) * 8) * 2;
    // V frag (trans): row = 16s + ((lane>>3)&1)*8 + (lane&7), col = ng*16 + (lane>>4)*8
    const uint32_t v_row = (uint32_t)(((lane >> 3) & 1) * 8 + (lane & 7));
    const uint32_t v_colb = (uint32_t)((lane >> 4) * 8) * 2;

    float o[8][4];
    #pragma unroll
    for (int t = 0; t < 8; ++t)
        #pragma unroll
        for (int q = 0; q < 4; ++q) o[t][q] = 0.f;
    float m0 = -INFINITY, m1 = -INFINITY, l0 = 0.f, l1 = 0.f;

    const int i0 = qt * 128 + wq + g;
    const int i1 = i0 + 8;
    const int jtmax = 2 * qt + 1;

    // tile loader indices
    const int lj = tid & 63;           // kv row in tile
    const int lq = tid >> 6;           // 0..3 -> 16-col group
    const size_t ld_base = (size_t)lj * (3 * C_) + lq * 16;
    const uint32_t lst = (uint32_t)lj * KSTR + lq * 32;

    for (int jt = 0; jt <= jtmax; ++jt) {
        __syncthreads();  // previous tile's ldmatrix reads done
        // ---- load K,V tile (64 rows x 64 cols), hi/lo split
        {
            const float* kp = kb + (size_t)jt * 64 * (3 * C_) + ld_base;
            const float* vp = vb + (size_t)jt * 64 * (3 * C_) + ld_base;
            float f[16];
            uint32_t hi[4], lo[4];
            #pragma unroll
            for (int q = 0; q < 4; ++q) *(float4*)(f + q * 4) = *(const float4*)(kp + q * 4);
            split8(f, hi, lo);
            *(uint4*)(smem + AKH + lst)      = make_uint4(hi[0], hi[1], hi[2], hi[3]);
            *(uint4*)(smem + AKL + lst)      = make_uint4(lo[0], lo[1], lo[2], lo[3]);
            split8(f + 8, hi, lo);
            *(uint4*)(smem + AKH + lst + 16) = make_uint4(hi[0], hi[1], hi[2], hi[3]);
            *(uint4*)(smem + AKL + lst + 16) = make_uint4(lo[0], lo[1], lo[2], lo[3]);
            #pragma unroll
            for (int q = 0; q < 4; ++q) *(float4*)(f + q * 4) = *(const float4*)(vp + q * 4);
            split8(f, hi, lo);
            *(uint4*)(smem + AVH + lst)      = make_uint4(hi[0], hi[1], hi[2], hi[3]);
            *(uint4*)(smem + AVL + lst)      = make_uint4(lo[0], lo[1], lo[2], lo[3]);
            split8(f + 8, hi, lo);
            *(uint4*)(smem + AVH + lst + 16) = make_uint4(hi[0], hi[1], hi[2], hi[3]);
            *(uint4*)(smem + AVL + lst + 16) = make_uint4(lo[0], lo[1], lo[2], lo[3]);
        }
        __syncthreads();

        // warps whose entire 16-row slab is masked for this tile: skip compute
        if (jt * 64 > qt * 128 + wq + 15) continue;

        // ---- S = Q K^T (bf16-split, fp32 accum)
        float sacc[8][4];
        #pragma unroll
        for (int t = 0; t < 8; ++t)
            #pragma unroll
            for (int q = 0; q < 4; ++q) sacc[t][q] = 0.f;

        #pragma unroll
        for (int s = 0; s < 4; ++s) {
            const uint32_t k0b = (uint32_t)(s * 16) * 2;
            #pragma unroll
            for (int np = 0; np < 4; ++np) {
                const uint32_t off = (uint32_t)(np * 16 + k_row) * KSTR + k0b + k_colb;
                uint32_t bH[4], bL[4];
                ldsm_x4(bH, sb + AKH + off);
                ldsm_x4(bL, sb + AKL + off);
                mma16816(sacc[2 * np],     qh[s], bH[0], bH[1]);
                mma16816(sacc[2 * np],     qh[s], bL[0], bL[1]);
                mma16816(sacc[2 * np],     ql[s], bH[0], bH[1]);
                mma16816(sacc[2 * np + 1], qh[s], bH[2], bH[3]);
                mma16816(sacc[2 * np + 1], qh[s], bL[2], bL[3]);
                mma16816(sacc[2 * np + 1], ql[s], bH[2], bH[3]);
            }
        }

        // ---- ALiBi bias + causal mask
        const bool needmask = (jt >= 2 * qt);
        #pragma unroll
        for (int t = 0; t < 8; ++t) {
            const int j0 = jt * 64 + t * 8 + 2 * c;
            sacc[t][0] += slope * (float)(i0 - j0);
            sacc[t][1] += slope * (float)(i0 - j0 - 1);
            sacc[t][2] += slope * (float)(i1 - j0);
            sacc[t][3] += slope * (float)(i1 - j0 - 1);
            if (needmask) {
                if (j0     > i0) sacc[t][0] = -INFINITY;
                if (j0 + 1 > i0) sacc[t][1] = -INFINITY;
                if (j0     > i1) sacc[t][2] = -INFINITY;
                if (j0 + 1 > i1) sacc[t][3] = -INFINITY;
            }
        }

        // ---- online softmax (rows g, g+8; quad shfl reduce)
        float rm0 = -INFINITY, rm1 = -INFINITY;
        #pragma unroll
        for (int t = 0; t < 8; ++t) {
            rm0 = fmaxf(rm0, fmaxf(sacc[t][0], sacc[t][1]));
            rm1 = fmaxf(rm1, fmaxf(sacc[t][2], sacc[t][3]));
        }
        rm0 = fmaxf(rm0, __shfl_xor_sync(0xffffffffu, rm0, 1));
        rm0 = fmaxf(rm0, __shfl_xor_sync(0xffffffffu, rm0, 2));
        rm1 = fmaxf(rm1, __shfl_xor_sync(0xffffffffu, rm1, 1));
        rm1 = fmaxf(rm1, __shfl_xor_sync(0xffffffffu, rm1, 2));
        const float mn0 = fmaxf(m0, rm0), mn1 = fmaxf(m1, rm1);
        const float c0 = __expf(m0 - mn0), c1 = __expf(m1 - mn1);
        m0 = mn0; m1 = mn1;

        uint32_t pAh[8], pAl[8], pBh[8], pBl[8];
        float s0 = 0.f, s1 = 0.f;
        #pragma unroll
        for (int t = 0; t < 8; ++t) {
            const float p0 = __expf(sacc[t][0] - mn0);
            const float p1 = __expf(sacc[t][1] - mn0);
            const float p2 = __expf(sacc[t][2] - mn1);
            const float p3 = __expf(sacc[t][3] - mn1);
            s0 += p0 + p1; s1 += p2 + p3;
            split2(p0, p1, pAh[t], pAl[t]);
            split2(p2, p3, pBh[t], pBl[t]);
        }
        l0 = l0 * c0 + s0;
        l1 = l1 * c1 + s1;
        #pragma unroll
        for (int t = 0; t < 8; ++t) {
            o[t][0] *= c0; o[t][1] *= c0;
            o[t][2] *= c1; o[t][3] *= c1;
        }

        // ---- O += P V (bf16-split)
        #pragma unroll
        for (int s = 0; s < 4; ++s) {
            const uint32_t aH[4] = {pAh[2 * s], pBh[2 * s], pAh[2 * s + 1], pBh[2 * s + 1]};
            const uint32_t aL[4] = {pAl[2 * s], pBl[2 * s], pAl[2 * s + 1], pBl[2 * s + 1]};
            const uint32_t rowb = (uint32_t)(s * 16 + v_row) * KSTR;
            #pragma unroll
            for (int ng = 0; ng < 4; ++ng) {
                const uint32_t off = rowb + (uint32_t)(ng * 16) * 2 + v_colb;
                uint32_t vH[4], vL[4];
                ldsm_x4_t(vH, sb + AVH + off);
                ldsm_x4_t(vL, sb + AVL + off);
                mma16816(o[2 * ng],     aH, vH[0], vH[1]);
                mma16816(o[2 * ng],     aH, vL[0], vL[1]);
                mma16816(o[2 * ng],     aL, vH[0], vH[1]);
                mma16816(o[2 * ng + 1], aH, vH[2], vH[3]);
                mma16816(o[2 * ng + 1], aH, vL[2], vL[3]);
                mma16816(o[2 * ng + 1], aL, vH[2], vH[3]);
            }
        }
    }

    // ---- finalize: reduce l over quad, normalize, store
    l0 += __shfl_xor_sync(0xffffffffu, l0, 1);
    l0 += __shfl_xor_sync(0xffffffffu, l0, 2);
    l1 += __shfl_xor_sync(0xffffffffu, l1, 1);
    l1 += __shfl_xor_sync(0xffffffffu, l1, 2);
    const float inv0 = 1.f / l0, inv1 = 1.f / l1;

    float* o0 = out + (size_t)(b * T_ + i0) * C_ + h * D_ + 2 * c;
    float* o1 = out + (size_t)(b * T_ + i1) * C_ + h * D_ + 2 * c;
    #pragma unroll
    for (int t = 0; t < 8; ++t) {
        *(float2*)(o0 + t * 8) = make_float2(o[t][0] * inv0, o[t][1] * inv0);
        *(float2*)(o1 + t * 8) = make_float2(o[t][2] * inv1, o[t][3] * inv1);
    }
}

// ---------------------------------------------------------------------------
extern "C" void kernel_launch(void* const* d_in, const int* in_sizes, int n_in,
                              void* d_out, int out_size)
{
    const float* x      = (const float*)d_in[0];  // [B,T,C]
    const float* w_qkv  = (const float*)d_in[1];  // [C,3C]
    const float* w_proj = (const float*)d_in[2];  // [C,C]
    float* out = (float*)d_out;                   // [B,T,C]

    float *qkv, *att;
    cudaGetSymbolAddress((void**)&qkv, g_qkv);
    cudaGetSymbolAddress((void**)&att, g_att);

    const int M = B_ * T_;  // 4096

    // 1) qkv = x @ w_qkv   [4096,1024]x[1024,3072]
    gemm_mma<<<dim3((3 * C_) / 128, M / 128), 256, GEMM_SMEM>>>(x, w_qkv, qkv, M, 3 * C_, C_);

    // 2) attention -> att [B,T,C]
    attn_mma<<<dim3(T_ / 128, B_ * H_), 256, ATTN_SMEM>>>(qkv, att);

    // 3) out = att @ w_proj [4096,1024]x[1024,1024]
    gemm_mma<<<dim3(C_ / 128, M / 128), 256, GEMM_SMEM>>>(att, w_proj, out, M, C_, C_);
}

// round 5
// speedup vs baseline: 2.7596x; 1.2532x over previous
#include <cuda_runtime.h>
#include <cuda_bf16.h>
#include <math.h>
#include <stdint.h>

#define B_ 2
#define T_ 2048
#define C_ 1024
#define H_ 16
#define D_ 64

// ---------------- scratch (allocation-free rule: __device__ globals) --------
__device__ __nv_bfloat16 g_xh[(size_t)B_ * T_ * C_];
__device__ __nv_bfloat16 g_xl[(size_t)B_ * T_ * C_];
__device__ __nv_bfloat16 g_wqh[(size_t)C_ * 3 * C_];
__device__ __nv_bfloat16 g_wql[(size_t)C_ * 3 * C_];
__device__ __nv_bfloat16 g_wph[(size_t)C_ * C_];
__device__ __nv_bfloat16 g_wpl[(size_t)C_ * C_];
__device__ __nv_bfloat16 g_qkvh[(size_t)B_ * T_ * 3 * C_];
__device__ __nv_bfloat16 g_qkvl[(size_t)B_ * T_ * 3 * C_];
__device__ __nv_bfloat16 g_ath[(size_t)B_ * T_ * C_];
__device__ __nv_bfloat16 g_atl[(size_t)B_ * T_ * C_];

// ---------------- helpers ----------------------------------------------------
__device__ __forceinline__ uint32_t smem_u32(const void* p) {
    uint32_t a;
    asm("{ .reg .u64 t; cvta.to.shared.u64 t, %1; cvt.u32.u64 %0, t; }"
        : "=r"(a) : "l"(p));
    return a;
}
__device__ __forceinline__ void ldsm_x4(uint32_t* r, uint32_t addr) {
    asm volatile("ldmatrix.sync.aligned.m8n8.x4.shared.b16 {%0,%1,%2,%3}, [%4];"
                 : "=r"(r[0]), "=r"(r[1]), "=r"(r[2]), "=r"(r[3]) : "r"(addr));
}
__device__ __forceinline__ void ldsm_x4_t(uint32_t* r, uint32_t addr) {
    asm volatile("ldmatrix.sync.aligned.m8n8.x4.trans.shared.b16 {%0,%1,%2,%3}, [%4];"
                 : "=r"(r[0]), "=r"(r[1]), "=r"(r[2]), "=r"(r[3]) : "r"(addr));
}
__device__ __forceinline__ void mma16816(float* d, const uint32_t* a,
                                         uint32_t b0, uint32_t b1) {
    asm volatile(
        "mma.sync.aligned.m16n8k16.row.col.f32.bf16.bf16.f32 "
        "{%0,%1,%2,%3}, {%4,%5,%6,%7}, {%8,%9}, {%0,%1,%2,%3};"
        : "+f"(d[0]), "+f"(d[1]), "+f"(d[2]), "+f"(d[3])
        : "r"(a[0]), "r"(a[1]), "r"(a[2]), "r"(a[3]), "r"(b0), "r"(b1));
}
__device__ __forceinline__ void cp16(uint32_t dst, const void* src) {
    asm volatile("cp.async.cg.shared.global [%0], [%1], 16;" :: "r"(dst), "l"(src));
}
#define CP_COMMIT() asm volatile("cp.async.commit_group;" ::: "memory")
#define CP_WAIT(n)  asm volatile("cp.async.wait_group %0;" :: "n"(n) : "memory")

__device__ __forceinline__ uint32_t pkbf2(__nv_bfloat16 a, __nv_bfloat16 b) {
    __nv_bfloat162 t(a, b);
    return *reinterpret_cast<uint32_t*>(&t);
}
__device__ __forceinline__ void split2(float a, float b, uint32_t& hi, uint32_t& lo) {
    const __nv_bfloat16 ha = __float2bfloat16(a);
    const __nv_bfloat16 hb = __float2bfloat16(b);
    hi = pkbf2(ha, hb);
    lo = pkbf2(__float2bfloat16(a - __bfloat162float(ha)),
               __float2bfloat16(b - __bfloat162float(hb)));
}

// ---------------- fp32 -> (hi, lo) bf16 elementwise split -------------------
__global__ __launch_bounds__(256) void split_kernel(
    const float* __restrict__ src, __nv_bfloat16* __restrict__ h,
    __nv_bfloat16* __restrict__ l, int n4)
{
    const int i = blockIdx.x * blockDim.x + threadIdx.x;
    if (i < n4) {
        const float4 f = ((const float4*)src)[i];
        uint32_t h0, l0, h1, l1;
        split2(f.x, f.y, h0, l0);
        split2(f.z, f.w, h1, l1);
        ((uint2*)h)[i] = make_uint2(h0, h1);
        ((uint2*)l)[i] = make_uint2(l0, l1);
    }
}

// ---------------------------------------------------------------------------
// bf16-split GEMM, pre-converted operands, cp.async double-buffered.
// C = A @ B ; A as (Ah,Al) [M,K] row-major bf16, B as (Bh,Bl) [K,N] row-major.
// CTA 128x128, BK=32, 256 thr (8 warps 4x2, warp tile 32x64).
// SPLIT_OUT=0: fp32 C. SPLIT_OUT=1: write (Ch,Cl) bf16 split.
// ---------------------------------------------------------------------------
#define G_AH 0
#define G_AL 10240                    /* 128 rows * 80B */
#define G_BH 20480
#define G_BL 29184                    /* 32 rows * 272B */
#define G_STAGE 37888
#define GEMM_SMEM (2 * G_STAGE)

template<int SPLIT_OUT>
__global__ __launch_bounds__(256, 2) void gemm_bf16(
    const __nv_bfloat16* __restrict__ Ah, const __nv_bfloat16* __restrict__ Al,
    const __nv_bfloat16* __restrict__ Bh, const __nv_bfloat16* __restrict__ Bl,
    float* __restrict__ Cf, __nv_bfloat16* __restrict__ Ch,
    __nv_bfloat16* __restrict__ Cl, int M, int N, int K)
{
    extern __shared__ __align__(128) char smem[];
    const uint32_t sb = smem_u32(smem);

    const int tid = threadIdx.x;
    const int wid = tid >> 5, lane = tid & 31;
    const int bm = blockIdx.y * 128, bn = blockIdx.x * 128;
    const int wm = (wid >> 1) * 32;
    const int wn = (wid & 1) * 64;
    const int t2 = tid * 2;

    // fragment address pieces
    const int a_r = wm + (lane & 15);
    const int a_c = (lane >> 4) * 8;
    const uint32_t b_row = (uint32_t)(((lane >> 3) & 1) * 8 + (lane & 7));
    const uint32_t b_colb = (uint32_t)((lane >> 4) * 8) * 2;

    float acc[2][8][4];
    #pragma unroll
    for (int mi = 0; mi < 2; ++mi)
        #pragma unroll
        for (int ni = 0; ni < 8; ++ni)
            #pragma unroll
            for (int q = 0; q < 4; ++q) acc[mi][ni][q] = 0.f;

    // stage loader: 8 cp16 per thread
    auto issue = [&](int ch, int stg) {
        const uint32_t st = sb + (uint32_t)stg * G_STAGE;
        #pragma unroll
        for (int u = 0; u < 2; ++u) {
            const int ia = t2 + u;
            const int ar = ia >> 2, ac = ia & 3;         // A: 128 rows x 4 chunks
            const __nv_bfloat16* sa = Ah + (size_t)(bm + ar) * K + ch * 32 + ac * 8;
            const __nv_bfloat16* sal = Al + (size_t)(bm + ar) * K + ch * 32 + ac * 8;
            cp16(st + G_AH + (uint32_t)ar * 80 + ac * 16, sa);
            cp16(st + G_AL + (uint32_t)ar * 80 + ac * 16, sal);
            const int br = ia >> 4, bc = ia & 15;        // B: 32 rows x 16 chunks
            const __nv_bfloat16* sbh = Bh + (size_t)(ch * 32 + br) * N + bn + bc * 8;
            const __nv_bfloat16* sbl = Bl + (size_t)(ch * 32 + br) * N + bn + bc * 8;
            cp16(st + G_BH + (uint32_t)br * 272 + bc * 16, sbh);
            cp16(st + G_BL + (uint32_t)br * 272 + bc * 16, sbl);
        }
        CP_COMMIT();
    };

    const int nchunks = K / 32;
    issue(0, 0);

    for (int ch = 0; ch < nchunks; ++ch) {
        if (ch + 1 < nchunks) { issue(ch + 1, (ch + 1) & 1); CP_WAIT(1); }
        else                  { CP_WAIT(0); }
        __syncthreads();

        const uint32_t st = sb + (uint32_t)(ch & 1) * G_STAGE;
        #pragma unroll
        for (int ks = 0; ks < 2; ++ks) {
            const int k0 = ks * 16;
            uint32_t aH[2][4], aL[2][4];
            #pragma unroll
            for (int mi = 0; mi < 2; ++mi) {
                const uint32_t ao = (uint32_t)(a_r + mi * 16) * 80 + (k0 + a_c) * 2;
                ldsm_x4(aH[mi], st + G_AH + ao);
                ldsm_x4(aL[mi], st + G_AL + ao);
            }
            #pragma unroll
            for (int j = 0; j < 4; ++j) {
                const uint32_t bo = (uint32_t)(k0 + b_row) * 272
                                  + (uint32_t)(wn + j * 16) * 2 + b_colb;
                uint32_t bH[4], bL[4];
                ldsm_x4_t(bH, st + G_BH + bo);
                ldsm_x4_t(bL, st + G_BL + bo);
                // interleave across 4 independent accumulators
                mma16816(acc[0][2 * j],     aH[0], bH[0], bH[1]);
                mma16816(acc[1][2 * j],     aH[1], bH[0], bH[1]);
                mma16816(acc[0][2 * j + 1], aH[0], bH[2], bH[3]);
                mma16816(acc[1][2 * j + 1], aH[1], bH[2], bH[3]);
                mma16816(acc[0][2 * j],     aH[0], bL[0], bL[1]);
                mma16816(acc[1][2 * j],     aH[1], bL[0], bL[1]);
                mma16816(acc[0][2 * j + 1], aH[0], bL[2], bL[3]);
                mma16816(acc[1][2 * j + 1], aH[1], bL[2], bL[3]);
                mma16816(acc[0][2 * j],     aL[0], bH[0], bH[1]);
                mma16816(acc[1][2 * j],     aL[1], bH[0], bH[1]);
                mma16816(acc[0][2 * j + 1], aL[0], bH[2], bH[3]);
                mma16816(acc[1][2 * j + 1], aL[1], bH[2], bH[3]);
            }
        }
        __syncthreads();
    }

    // epilogue
    const int g = lane >> 2, cpair = (lane & 3) * 2;
    #pragma unroll
    for (int mi = 0; mi < 2; ++mi) {
        #pragma unroll
        for (int ni = 0; ni < 8; ++ni) {
            const size_t r0 = (size_t)(bm + wm + mi * 16 + g) * N + bn + wn + ni * 8 + cpair;
            const size_t r1 = r0 + (size_t)8 * N;
            if (SPLIT_OUT) {
                uint32_t h0, l0, h1, l1;
                split2(acc[mi][ni][0], acc[mi][ni][1], h0, l0);
                split2(acc[mi][ni][2], acc[mi][ni][3], h1, l1);
                *(uint32_t*)(Ch + r0) = h0;
                *(uint32_t*)(Cl + r0) = l0;
                *(uint32_t*)(Ch + r1) = h1;
                *(uint32_t*)(Cl + r1) = l1;
            } else {
                *(float2*)(Cf + r0) = make_float2(acc[mi][ni][0], acc[mi][ni][1]);
                *(float2*)(Cf + r1) = make_float2(acc[mi][ni][2], acc[mi][ni][3]);
            }
        }
    }
}

// ---------------------------------------------------------------------------
// Flash-attention on mma.sync, pre-split bf16 QKV, cp.async double-buffered.
// CTA: 128 Q rows x one (b,h); warp owns 16 rows; softmax warp-local.
// Scale 1/8 applied post-MMA (exact). Output written as (hi,lo) bf16.
// ---------------------------------------------------------------------------
#define A_KH 0
#define A_KL 9216                     /* 64 rows * 144B */
#define A_VH 18432
#define A_VL 27648
#define A_STAGE 36864
#define ATTN_SMEM (2 * A_STAGE)

__global__ __launch_bounds__(256) void attn_mma(
    const __nv_bfloat16* __restrict__ qkvh, const __nv_bfloat16* __restrict__ qkvl,
    __nv_bfloat16* __restrict__ oh, __nv_bfloat16* __restrict__ ol)
{
    extern __shared__ __align__(128) char smem[];
    const uint32_t sb = smem_u32(smem);

    const int qt = blockIdx.x;        // 0..15
    const int bh = blockIdx.y;        // 0..31
    const int b = bh >> 4, h = bh & 15;
    const int tid = threadIdx.x;
    const int wid = tid >> 5, lane = tid & 31;
    const int g = lane >> 2, c = lane & 3;
    const int wq = wid * 16;
    const int t2 = tid * 2;

    const float slope = exp2f(-0.5f * (float)(h + 1));

    const size_t bbase = (size_t)b * T_ * 3 * C_;
    const int i0 = qt * 128 + wq + g;
    const int i1 = i0 + 8;

    // ---- Q fragments: direct u32 loads from pre-split arrays
    uint32_t qh[4][4], ql[4][4];
    {
        const __nv_bfloat16* qh0 = qkvh + bbase + (size_t)i0 * (3 * C_) + h * D_;
        const __nv_bfloat16* ql0 = qkvl + bbase + (size_t)i0 * (3 * C_) + h * D_;
        #pragma unroll
        for (int s = 0; s < 4; ++s) {
            const int k0 = s * 16 + 2 * c;
            qh[s][0] = *(const uint32_t*)(qh0 + k0);
            qh[s][1] = *(const uint32_t*)(qh0 + (size_t)8 * 3 * C_ + k0);
            qh[s][2] = *(const uint32_t*)(qh0 + k0 + 8);
            qh[s][3] = *(const uint32_t*)(qh0 + (size_t)8 * 3 * C_ + k0 + 8);
            ql[s][0] = *(const uint32_t*)(ql0 + k0);
            ql[s][1] = *(const uint32_t*)(ql0 + (size_t)8 * 3 * C_ + k0);
            ql[s][2] = *(const uint32_t*)(ql0 + k0 + 8);
            ql[s][3] = *(const uint32_t*)(ql0 + (size_t)8 * 3 * C_ + k0 + 8);
        }
    }

    const uint32_t k_row = (uint32_t)((lane >> 4) * 8 + (lane & 7));
    const uint32_t k_colb = (uint32_t)(((lane >> 3) & 1) * 8) * 2;
    const uint32_t v_row = (uint32_t)(((lane >> 3) & 1) * 8 + (lane & 7));
    const uint32_t v_colb = (uint32_t)((lane >> 4) * 8) * 2;

    float o[8][4];
    #pragma unroll
    for (int t = 0; t < 8; ++t)
        #pragma unroll
        for (int q = 0; q < 4; ++q) o[t][q] = 0.f;
    float m0 = -INFINITY, m1 = -INFINITY, l0 = 0.f, l1 = 0.f;

    const int jtmax = 2 * qt + 1;

    auto issue = [&](int jt, int stg) {
        const uint32_t st = sb + (uint32_t)stg * A_STAGE;
        #pragma unroll
        for (int u = 0; u < 2; ++u) {
            const int ia = t2 + u;
            const int row = ia >> 3, ch = ia & 7;        // 64 rows x 8 chunks
            const size_t go = bbase + (size_t)(jt * 64 + row) * (3 * C_) + h * D_ + ch * 8;
            const uint32_t so = (uint32_t)row * 144 + ch * 16;
            cp16(st + A_KH + so, qkvh + go + C_);
            cp16(st + A_KL + so, qkvl + go + C_);
            cp16(st + A_VH + so, qkvh + go + 2 * C_);
            cp16(st + A_VL + so, qkvl + go + 2 * C_);
        }
        CP_COMMIT();
    };

    issue(0, 0);

    for (int jt = 0; jt <= jtmax; ++jt) {
        if (jt < jtmax) { issue(jt + 1, (jt + 1) & 1); CP_WAIT(1); }
        else            { CP_WAIT(0); }
        __syncthreads();

        const bool active = (jt * 64 <= qt * 128 + wq + 15);
        if (active) {
            const uint32_t st = sb + (uint32_t)(jt & 1) * A_STAGE;

            // ---- S = Q K^T
            float sacc[8][4];
            #pragma unroll
            for (int t = 0; t < 8; ++t)
                #pragma unroll
                for (int q = 0; q < 4; ++q) sacc[t][q] = 0.f;

            #pragma unroll
            for (int s = 0; s < 4; ++s) {
                const uint32_t k0b = (uint32_t)(s * 16) * 2;
                #pragma unroll
                for (int np = 0; np < 4; ++np) {
                    const uint32_t off = (uint32_t)(np * 16 + k_row) * 144 + k0b + k_colb;
                    uint32_t bH[4], bL[4];
                    ldsm_x4(bH, st + A_KH + off);
                    ldsm_x4(bL, st + A_KL + off);
                    mma16816(sacc[2 * np],     qh[s], bH[0], bH[1]);
                    mma16816(sacc[2 * np + 1], qh[s], bH[2], bH[3]);
                    mma16816(sacc[2 * np],     qh[s], bL[0], bL[1]);
                    mma16816(sacc[2 * np + 1], qh[s], bL[2], bL[3]);
                    mma16816(sacc[2 * np],     ql[s], bH[0], bH[1]);
                    mma16816(sacc[2 * np + 1], ql[s], bH[2], bH[3]);
                }
            }

            // ---- scale + ALiBi + causal mask
            const bool needmask = (jt >= 2 * qt);
            #pragma unroll
            for (int t = 0; t < 8; ++t) {
                const int j0 = jt * 64 + t * 8 + 2 * c;
                sacc[t][0] = fmaf(sacc[t][0], 0.125f, slope * (float)(i0 - j0));
                sacc[t][1] = fmaf(sacc[t][1], 0.125f, slope * (float)(i0 - j0 - 1));
                sacc[t][2] = fmaf(sacc[t][2], 0.125f, slope * (float)(i1 - j0));
                sacc[t][3] = fmaf(sacc[t][3], 0.125f, slope * (float)(i1 - j0 - 1));
                if (needmask) {
                    if (j0     > i0) sacc[t][0] = -INFINITY;
                    if (j0 + 1 > i0) sacc[t][1] = -INFINITY;
                    if (j0     > i1) sacc[t][2] = -INFINITY;
                    if (j0 + 1 > i1) sacc[t][3] = -INFINITY;
                }
            }

            // ---- online softmax
            float rm0 = -INFINITY, rm1 = -INFINITY;
            #pragma unroll
            for (int t = 0; t < 8; ++t) {
                rm0 = fmaxf(rm0, fmaxf(sacc[t][0], sacc[t][1]));
                rm1 = fmaxf(rm1, fmaxf(sacc[t][2], sacc[t][3]));
            }
            rm0 = fmaxf(rm0, __shfl_xor_sync(0xffffffffu, rm0, 1));
            rm0 = fmaxf(rm0, __shfl_xor_sync(0xffffffffu, rm0, 2));
            rm1 = fmaxf(rm1, __shfl_xor_sync(0xffffffffu, rm1, 1));
            rm1 = fmaxf(rm1, __shfl_xor_sync(0xffffffffu, rm1, 2));
            const float mn0 = fmaxf(m0, rm0), mn1 = fmaxf(m1, rm1);
            const float c0 = __expf(m0 - mn0), c1 = __expf(m1 - mn1);
            m0 = mn0; m1 = mn1;

            uint32_t pAh[8], pAl[8], pBh[8], pBl[8];
            float s0 = 0.f, s1 = 0.f;
            #pragma unroll
            for (int t = 0; t < 8; ++t) {
                const float p0 = __expf(sacc[t][0] - mn0);
                const float p1 = __expf(sacc[t][1] - mn0);
                const float p2 = __expf(sacc[t][2] - mn1);
                const float p3 = __expf(sacc[t][3] - mn1);
                s0 += p0 + p1; s1 += p2 + p3;
                split2(p0, p1, pAh[t], pAl[t]);
                split2(p2, p3, pBh[t], pBl[t]);
            }
            l0 = l0 * c0 + s0;
            l1 = l1 * c1 + s1;
            #pragma unroll
            for (int t = 0; t < 8; ++t) {
                o[t][0] *= c0; o[t][1] *= c0;
                o[t][2] *= c1; o[t][3] *= c1;
            }

            // ---- O += P V
            #pragma unroll
            for (int s = 0; s < 4; ++s) {
                const uint32_t aH[4] = {pAh[2 * s], pBh[2 * s], pAh[2 * s + 1], pBh[2 * s + 1]};
                const uint32_t aL[4] = {pAl[2 * s], pBl[2 * s], pAl[2 * s + 1], pBl[2 * s + 1]};
                const uint32_t rowb = (uint32_t)(s * 16 + v_row) * 144;
                #pragma unroll
                for (int ng = 0; ng < 4; ++ng) {
                    const uint32_t off = rowb + (uint32_t)(ng * 16) * 2 + v_colb;
                    uint32_t vH[4], vL[4];
                    ldsm_x4_t(vH, st + A_VH + off);
                    ldsm_x4_t(vL, st + A_VL + off);
                    mma16816(o[2 * ng],     aH, vH[0], vH[1]);
                    mma16816(o[2 * ng + 1], aH, vH[2], vH[3]);
                    mma16816(o[2 * ng],     aH, vL[0], vL[1]);
                    mma16816(o[2 * ng + 1], aH, vL[2], vL[3]);
                    mma16816(o[2 * ng],     aL, vH[0], vH[1]);
                    mma16816(o[2 * ng + 1], aL, vH[2], vH[3]);
                }
            }
        }
        __syncthreads();
    }

    // ---- finalize: write (hi, lo) bf16 for proj GEMM
    l0 += __shfl_xor_sync(0xffffffffu, l0, 1);
    l0 += __shfl_xor_sync(0xffffffffu, l0, 2);
    l1 += __shfl_xor_sync(0xffffffffu, l1, 1);
    l1 += __shfl_xor_sync(0xffffffffu, l1, 2);
    const float inv0 = 1.f / l0, inv1 = 1.f / l1;

    const size_t r0 = (size_t)(b * T_ + i0) * C_ + h * D_ + 2 * c;
    const size_t r1 = (size_t)(b * T_ + i1) * C_ + h * D_ + 2 * c;
    #pragma unroll
    for (int t = 0; t < 8; ++t) {
        uint32_t h0, lw0, h1, lw1;
        split2(o[t][0] * inv0, o[t][1] * inv0, h0, lw0);
        split2(o[t][2] * inv1, o[t][3] * inv1, h1, lw1);
        *(uint32_t*)(oh + r0 + t * 8) = h0;
        *(uint32_t*)(ol + r0 + t * 8) = lw0;
        *(uint32_t*)(oh + r1 + t * 8) = h1;
        *(uint32_t*)(ol + r1 + t * 8) = lw1;
    }
}

// ---------------------------------------------------------------------------
extern "C" void kernel_launch(void* const* d_in, const int* in_sizes, int n_in,
                              void* d_out, int out_size)
{
    const float* x      = (const float*)d_in[0];  // [B,T,C]
    const float* w_qkv  = (const float*)d_in[1];  // [C,3C]
    const float* w_proj = (const float*)d_in[2];  // [C,C]
    float* out = (float*)d_out;                   // [B,T,C]

    __nv_bfloat16 *xh, *xl, *wqh, *wql, *wph, *wpl, *qkvh, *qkvl, *ath, *atl;
    cudaGetSymbolAddress((void**)&xh, g_xh);
    cudaGetSymbolAddress((void**)&xl, g_xl);
    cudaGetSymbolAddress((void**)&wqh, g_wqh);
    cudaGetSymbolAddress((void**)&wql, g_wql);
    cudaGetSymbolAddress((void**)&wph, g_wph);
    cudaGetSymbolAddress((void**)&wpl, g_wpl);
    cudaGetSymbolAddress((void**)&qkvh, g_qkvh);
    cudaGetSymbolAddress((void**)&qkvl, g_qkvl);
    cudaGetSymbolAddress((void**)&ath, g_ath);
    cudaGetSymbolAddress((void**)&atl, g_atl);

    cudaFuncSetAttribute(gemm_bf16<0>, cudaFuncAttributeMaxDynamicSharedMemorySize, GEMM_SMEM);
    cudaFuncSetAttribute(gemm_bf16<1>, cudaFuncAttributeMaxDynamicSharedMemorySize, GEMM_SMEM);
    cudaFuncSetAttribute(attn_mma, cudaFuncAttributeMaxDynamicSharedMemorySize, ATTN_SMEM);

    const int M = B_ * T_;  // 4096

    // 0) pre-split inputs to (hi, lo) bf16
    split_kernel<<<(M * C_ / 4 + 255) / 256, 256>>>(x, xh, xl, M * C_ / 4);
    split_kernel<<<(C_ * 3 * C_ / 4 + 255) / 256, 256>>>(w_qkv, wqh, wql, C_ * 3 * C_ / 4);
    split_kernel<<<(C_ * C_ / 4 + 255) / 256, 256>>>(w_proj, wph, wpl, C_ * C_ / 4);

    // 1) qkv = x @ w_qkv  -> (hi, lo) bf16
    gemm_bf16<1><<<dim3((3 * C_) / 128, M / 128), 256, GEMM_SMEM>>>(
        xh, xl, wqh, wql, nullptr, qkvh, qkvl, M, 3 * C_, C_);

    // 2) attention -> (hi, lo) bf16
    attn_mma<<<dim3(T_ / 128, B_ * H_), 256, ATTN_SMEM>>>(qkvh, qkvl, ath, atl);

    // 3) out = att @ w_proj  -> fp32
    gemm_bf16<0><<<dim3(C_ / 128, M / 128), 256, GEMM_SMEM>>>(
        ath, atl, wph, wpl, out, nullptr, nullptr, M, C_, C_);
}